// round 4
// baseline (speedup 1.0000x reference)
#include <cuda_runtime.h>
#include <math.h>

typedef unsigned long long u64;

#define NT   4096   // B*T
#define CC   128    // n_embed
#define TT   32     // block_size
#define NH   4      // heads
#define HS   32     // head size
#define NE   4      // experts
#define NL   4      // layers
#define VV   50257  // vocab
#define FF   512    // 4*C

// -------------------- scratch (device globals; no allocs allowed) ---------
__device__ float g_x   [NT*CC];
__device__ float g_h   [NT*CC];
__device__ float g_qkv [NT*3*CC];
__device__ float g_att [NT*CC];
__device__ float g_nx  [NT*CC];
__device__ float g_moe [NT*CC];
__device__ float g_h1  [NT*FF];
__device__ float g_gates[NT*NE];
__device__ int   g_skip[NT];
__device__ float g_wpack[CC*3*CC];

// -------------------- threefry2x32 (JAX-compatible) -----------------------
__device__ __forceinline__ unsigned rotl32(unsigned v, int r){ return (v<<r)|(v>>(32-r)); }

__device__ void threefry2x32(unsigned k0, unsigned k1, unsigned x0, unsigned x1,
                             unsigned &o0, unsigned &o1)
{
    unsigned ks0=k0, ks1=k1, ks2 = k0 ^ k1 ^ 0x1BD11BDAu;
    x0 += ks0; x1 += ks1;
#define TF_RND(r) { x0 += x1; x1 = rotl32(x1, r); x1 ^= x0; }
    TF_RND(13) TF_RND(15) TF_RND(26) TF_RND(6)
    x0 += ks1; x1 += ks2 + 1u;
    TF_RND(17) TF_RND(29) TF_RND(16) TF_RND(24)
    x0 += ks2; x1 += ks0 + 2u;
    TF_RND(13) TF_RND(15) TF_RND(26) TF_RND(6)
    x0 += ks0; x1 += ks1 + 3u;
    TF_RND(17) TF_RND(29) TF_RND(16) TF_RND(24)
    x0 += ks1; x1 += ks2 + 4u;
    TF_RND(13) TF_RND(15) TF_RND(26) TF_RND(6)
    x0 += ks2; x1 += ks0 + 5u;
#undef TF_RND
    o0 = x0; o1 = x1;
}

// XLA ErfInv f32 (Giles polynomial)
__device__ float erfinv_f(float x)
{
    float w = -log1pf(-x*x);
    float p;
    if (w < 5.0f) {
        w = w - 2.5f;
        p =               2.81022636e-08f;
        p = fmaf(p, w,    3.43273939e-07f);
        p = fmaf(p, w,   -3.5233877e-06f);
        p = fmaf(p, w,   -4.39150654e-06f);
        p = fmaf(p, w,    0.00021858087f);
        p = fmaf(p, w,   -0.00125372503f);
        p = fmaf(p, w,   -0.00417768164f);
        p = fmaf(p, w,    0.246640727f);
        p = fmaf(p, w,    1.50140941f);
    } else {
        w = sqrtf(w) - 3.0f;
        p =              -0.000200214257f;
        p = fmaf(p, w,    0.000100950558f);
        p = fmaf(p, w,    0.00134934322f);
        p = fmaf(p, w,   -0.00367342844f);
        p = fmaf(p, w,    0.00573950773f);
        p = fmaf(p, w,   -0.0076224613f);
        p = fmaf(p, w,    0.00943887047f);
        p = fmaf(p, w,    1.00167406f);
        p = fmaf(p, w,    2.83297682f);
    }
    return p * x;
}

// jax.random.normal element i of key(42), partitionable scheme (JAX default):
//   (b1, b2) = threefry2x32(key, (hi=0, lo=i));  bits = b1 ^ b2   <-- XOR, fixed
// Flip NOISE_SCHEME to 0 for the legacy split-counter stream if needed.
#define NOISE_SCHEME 1
__device__ float jax_normal_elem(unsigned i)
{
    unsigned y0, y1, bits;
#if NOISE_SCHEME
    threefry2x32(0u, 42u, 0u, i, y0, y1);
    bits = y0 ^ y1;                    // _threefry_random_bits_partitionable, bit_width=32
#else
    unsigned j = i & 32767u, word = i >> 15;
    threefry2x32(0u, 42u, j, j + 32768u, y0, y1);
    bits = word ? y1 : y0;
#endif
    float f  = __uint_as_float((bits >> 9) | 0x3f800000u) - 1.0f;   // [0,1)
    const float lo = -0.99999994f;                                  // nextafter(-1,0)
    float u = fmaxf(lo, fmaf(f, 2.0f, lo));                         // maxval-minval -> 2.0f in fp32
    return 1.41421356f * erfinv_f(u);
}

// -------------------- small kernels ---------------------------------------
__global__ void embed_k(const int* __restrict__ idx, const float* __restrict__ tok,
                        const float* __restrict__ pos, float* __restrict__ x)
{
    int gid = blockIdx.x * blockDim.x + threadIdx.x;   // NT*CC
    int r = gid >> 7, c = gid & 127;
    int t = r & (TT - 1);
    x[gid] = tok[idx[r] * CC + c] + pos[t * CC + c];
}

__global__ void layernorm_k(const float* __restrict__ x, const float* __restrict__ g,
                            const float* __restrict__ b, float* __restrict__ out)
{
    int row = blockIdx.x, c = threadIdx.x;             // 128 threads
    __shared__ float red[CC];
    float v = x[row * CC + c];
    red[c] = v; __syncthreads();
    for (int s = 64; s > 0; s >>= 1) { if (c < s) red[c] += red[c + s]; __syncthreads(); }
    float mean = red[0] * (1.0f / CC);
    __syncthreads();
    float d = v - mean;
    red[c] = d * d; __syncthreads();
    for (int s = 64; s > 0; s >>= 1) { if (c < s) red[c] += red[c + s]; __syncthreads(); }
    float var = red[0] * (1.0f / CC);
    out[row * CC + c] = d / sqrtf(var + 1e-5f) * g[c] + b[c];
}

__global__ void pack_qkv_k(const float* __restrict__ Wq, const float* __restrict__ Wk,
                           const float* __restrict__ Wv, float* __restrict__ wp)
{
    int gid = blockIdx.x * blockDim.x + threadIdx.x;   // CC*384
    int c = gid / 384, j = gid % 384;
    const float* W = (j < 128) ? Wq : (j < 256 ? Wk : Wv);
    int jj = j & 127;
    int hh = jj >> 5, dd = jj & 31;
    wp[gid] = W[(hh * CC + c) * HS + dd];              // W[h,c,d] -> wp[c, h*32+d]
}

__global__ void attention_k(const float* __restrict__ qkv, float* __restrict__ att)
{
    int b = blockIdx.x >> 2, h = blockIdx.x & 3;
    int t = threadIdx.y, s = threadIdx.x;              // 32x32 threads
    __shared__ float qs[TT][HS+1], ks[TT][HS+1], vs[TT][HS+1], ws[TT][TT+1];
    int base = (b * TT + t) * (3 * CC) + h * HS;
    qs[t][s] = qkv[base + s];
    ks[t][s] = qkv[base + CC + s];
    vs[t][s] = qkv[base + 2 * CC + s];
    __syncthreads();
    const float NEG_INF = __int_as_float(0xff800000);
    float w;
    if (s <= t) {
        float acc = 0.f;
#pragma unroll
        for (int d = 0; d < HS; d++) acc = fmaf(qs[t][d], ks[s][d], acc);
        w = acc * 0.08838834764831845f;                // C^-0.5 (full C=128!)
    } else w = NEG_INF;
    float m = w;
#pragma unroll
    for (int o = 16; o; o >>= 1) m = fmaxf(m, __shfl_xor_sync(0xffffffffu, m, o));
    float e = (s <= t) ? expf(w - m) : 0.f;
    float sum = e;
#pragma unroll
    for (int o = 16; o; o >>= 1) sum += __shfl_xor_sync(0xffffffffu, sum, o);
    ws[t][s] = e / sum;
    __syncthreads();
    float acc = 0.f;
#pragma unroll
    for (int k = 0; k < TT; k++) acc = fmaf(ws[t][k], vs[k][s], acc);   // s plays 'd'
    att[(b * TT + t) * CC + h * HS + s] = acc;
}

__global__ void router_k(const float* __restrict__ nx,
                         const float* __restrict__ Wr, const float* __restrict__ br,
                         const float* __restrict__ Wn, const float* __restrict__ bn,
                         const float* __restrict__ Ws, const float* __restrict__ bs,
                         float* __restrict__ gates, int* __restrict__ skip, int layer)
{
    int row = blockIdx.x, c = threadIdx.x;             // 128 threads
    __shared__ float red[9][CC];
    float v = nx[row * CC + c];
#pragma unroll
    for (int e = 0; e < NE; e++) {
        red[e][c]     = v * Wr[c * NE + e];
        red[4 + e][c] = v * Wn[c * NE + e];
    }
    red[8][c] = v * Ws[c];
    __syncthreads();
    for (int st = 64; st > 0; st >>= 1) {
        if (c < st) {
#pragma unroll
            for (int j = 0; j < 9; j++) red[j][c] += red[j][c + st];
        }
        __syncthreads();
    }
    if (c == 0) {
        float noisy[NE];
#pragma unroll
        for (int e = 0; e < NE; e++) {
            float logit = red[e][0] + br[e];
            float nl    = red[4 + e][0] + bn[e];
            float sp    = fmaxf(nl, 0.f) + log1pf(expf(-fabsf(nl)));   // softplus
            unsigned i  = ((unsigned)(layer * NT + row)) * NE + e;
            noisy[e]    = logit + jax_normal_elem(i) * sp;
        }
        int i1 = 0;
        for (int e = 1; e < NE; e++) if (noisy[e] > noisy[i1]) i1 = e;
        int i2 = -1;
        for (int e = 0; e < NE; e++) if (e != i1 && (i2 < 0 || noisy[e] > noisy[i2])) i2 = e;
        float mx = noisy[i1];
        float gv[NE], gsum = 0.f;
#pragma unroll
        for (int e = 0; e < NE; e++) {
            gv[e] = (e == i1 || e == i2) ? expf(noisy[e] - mx) : 0.f;
            gsum += gv[e];
        }
#pragma unroll
        for (int e = 0; e < NE; e++) gates[row * NE + e] = gv[e] / gsum;
        skip[row] = (red[8][0] + bs[0] > 0.f) ? 1 : 0;  // sigmoid(z)>0.5 <=> z>0
    }
}

__global__ void combine_k(float* __restrict__ x, const float* __restrict__ moe,
                          const int* __restrict__ skip)
{
    int gid = blockIdx.x * blockDim.x + threadIdx.x;
    if (!skip[gid >> 7]) x[gid] += moe[gid];
}

// -------------------- SGEMM with f32x2 packed FMA -------------------------
#define BM 64
#define BN 64
#define BK 16
enum { EPI_BIAS = 0, EPI_RELU = 1, EPI_RESID = 2, EPI_GATE_WR = 3, EPI_GATE_ACC = 4 };

__device__ __forceinline__ void ffma2(u64 &d, u64 a, u64 b)
{
    asm("fma.rn.f32x2 %0, %1, %2, %0;" : "+l"(d) : "l"(a), "l"(b));
}

template<int EPI>
__global__ void __launch_bounds__(256, 4)
sgemm_k(const float* __restrict__ A, const float* __restrict__ B,
        const float* __restrict__ bias, float* __restrict__ C,
        int M, int N, int K, const float* __restrict__ gates, int gstride)
{
    __shared__ float2 As2[BK][BM];   // splatted {a,a} so FFMA2 needs no movs
    __shared__ float  Bs [BK][BN];
    int tid = threadIdx.x;
    int n0 = blockIdx.x * BN, m0 = blockIdx.y * BM;
    int tx = tid & 15, ty = tid >> 4;
    int am = tid >> 2,  ak = (tid & 3) * 4;   // A tile load coords
    int bk = tid >> 4,  bn = (tid & 15) * 4;  // B tile load coords

    u64 acc[4][2];
#pragma unroll
    for (int i = 0; i < 4; i++) { acc[i][0] = 0ull; acc[i][1] = 0ull; }

    for (int k0 = 0; k0 < K; k0 += BK) {
        float4 av = *reinterpret_cast<const float4*>(&A[(size_t)(m0 + am) * K + k0 + ak]);
        As2[ak + 0][am] = make_float2(av.x, av.x);
        As2[ak + 1][am] = make_float2(av.y, av.y);
        As2[ak + 2][am] = make_float2(av.z, av.z);
        As2[ak + 3][am] = make_float2(av.w, av.w);
        const float* Brow = &B[(size_t)(k0 + bk) * N + n0 + bn];
        if (n0 + BN <= N) {
            Bs[bk][bn + 0] = Brow[0]; Bs[bk][bn + 1] = Brow[1];
            Bs[bk][bn + 2] = Brow[2]; Bs[bk][bn + 3] = Brow[3];
        } else {
#pragma unroll
            for (int j = 0; j < 4; j++)
                Bs[bk][bn + j] = (n0 + bn + j < N) ? Brow[j] : 0.f;
        }
        __syncthreads();
#pragma unroll
        for (int k = 0; k < BK; k++) {
            u64 a[4];
#pragma unroll
            for (int i = 0; i < 4; i++)
                a[i] = *reinterpret_cast<const u64*>(&As2[k][ty * 4 + i]);
            ulonglong2 bv = *reinterpret_cast<const ulonglong2*>(&Bs[k][tx * 4]);
#pragma unroll
            for (int i = 0; i < 4; i++) {
                ffma2(acc[i][0], a[i], bv.x);
                ffma2(acc[i][1], a[i], bv.y);
            }
        }
        __syncthreads();
    }

#pragma unroll
    for (int i = 0; i < 4; i++) {
        int m = m0 + ty * 4 + i;
        float gate = 0.f;
        if (EPI == EPI_GATE_WR || EPI == EPI_GATE_ACC) gate = gates[(size_t)m * gstride];
#pragma unroll
        for (int p = 0; p < 2; p++) {
            float vlo = __uint_as_float((unsigned)(acc[i][p] & 0xffffffffull));
            float vhi = __uint_as_float((unsigned)(acc[i][p] >> 32));
#pragma unroll
            for (int q = 0; q < 2; q++) {
                int n = n0 + tx * 4 + p * 2 + q;
                if (n >= N) continue;
                float val = (q == 0 ? vlo : vhi) + (bias ? bias[n] : 0.f);
                size_t o = (size_t)m * N + n;
                if      (EPI == EPI_BIAS)     C[o] = val;
                else if (EPI == EPI_RELU)     C[o] = fmaxf(val, 0.f);
                else if (EPI == EPI_RESID)    C[o] = C[o] + val;
                else if (EPI == EPI_GATE_WR)  C[o] = gate * val;
                else                          C[o] += gate * val;
            }
        }
    }
}

// -------------------- host orchestration ----------------------------------
extern "C" void kernel_launch(void* const* d_in, const int* in_sizes, int n_in,
                              void* d_out, int out_size)
{
    (void)in_sizes; (void)n_in; (void)out_size;
    const int*   idx  = (const int*)  d_in[0];
    const float* tok  = (const float*)d_in[1];
    const float* pos  = (const float*)d_in[2];
    const float* ln1g = (const float*)d_in[3];
    const float* ln1b = (const float*)d_in[4];
    const float* Wq   = (const float*)d_in[5];
    const float* Wk   = (const float*)d_in[6];
    const float* Wv   = (const float*)d_in[7];
    const float* Wo   = (const float*)d_in[8];
    const float* bo   = (const float*)d_in[9];
    const float* ln2g = (const float*)d_in[10];
    const float* ln2b = (const float*)d_in[11];
    const float* Wr   = (const float*)d_in[12];
    const float* br   = (const float*)d_in[13];
    const float* Wn   = (const float*)d_in[14];
    const float* bn   = (const float*)d_in[15];
    const float* Wsr  = (const float*)d_in[16];
    const float* bsr  = (const float*)d_in[17];
    const float* W1   = (const float*)d_in[18];
    const float* b1   = (const float*)d_in[19];
    const float* W2   = (const float*)d_in[20];
    const float* b2   = (const float*)d_in[21];
    const float* lnfg = (const float*)d_in[22];
    const float* lnfb = (const float*)d_in[23];
    const float* Wlm  = (const float*)d_in[24];
    const float* blm  = (const float*)d_in[25];
    float* out = (float*)d_out;

    float *x, *h, *qkv, *att, *nx, *moe, *h1, *gates, *wp; int* skip;
    cudaGetSymbolAddress((void**)&x,     g_x);
    cudaGetSymbolAddress((void**)&h,     g_h);
    cudaGetSymbolAddress((void**)&qkv,   g_qkv);
    cudaGetSymbolAddress((void**)&att,   g_att);
    cudaGetSymbolAddress((void**)&nx,    g_nx);
    cudaGetSymbolAddress((void**)&moe,   g_moe);
    cudaGetSymbolAddress((void**)&h1,    g_h1);
    cudaGetSymbolAddress((void**)&gates, g_gates);
    cudaGetSymbolAddress((void**)&skip,  g_skip);
    cudaGetSymbolAddress((void**)&wp,    g_wpack);

    embed_k<<<NT * CC / 256, 256>>>(idx, tok, pos, x);

    for (int l = 0; l < NL; l++) {
        layernorm_k<<<NT, CC>>>(x, ln1g + l * CC, ln1b + l * CC, h);
        pack_qkv_k<<<CC * 384 / 256, 256>>>(Wq + l * NH * CC * HS, Wk + l * NH * CC * HS,
                                            Wv + l * NH * CC * HS, wp);
        sgemm_k<EPI_BIAS><<<dim3(384 / BN, NT / BM), 256>>>(h, wp, nullptr, qkv,
                                                            NT, 384, CC, nullptr, 0);
        attention_k<<<NT / TT * NH, dim3(32, 32)>>>(qkv, att);
        sgemm_k<EPI_RESID><<<dim3(CC / BN, NT / BM), 256>>>(att, Wo + l * CC * CC,
                                                            bo + l * CC, x, NT, CC, CC, nullptr, 0);
        layernorm_k<<<NT, CC>>>(x, ln2g + l * CC, ln2b + l * CC, nx);
        router_k<<<NT, CC>>>(nx, Wr + l * CC * NE, br + l * NE,
                             Wn + l * CC * NE, bn + l * NE,
                             Wsr + l * CC, bsr + l, gates, skip, l);
        for (int e = 0; e < NE; e++) {
            const float* w1e = W1 + (size_t)(l * NE + e) * CC * FF;
            const float* b1e = b1 + (size_t)(l * NE + e) * FF;
            const float* w2e = W2 + (size_t)(l * NE + e) * FF * CC;
            const float* b2e = b2 + (size_t)(l * NE + e) * CC;
            sgemm_k<EPI_RELU><<<dim3(FF / BN, NT / BM), 256>>>(nx, w1e, b1e, h1,
                                                               NT, FF, CC, nullptr, 0);
            if (e == 0)
                sgemm_k<EPI_GATE_WR><<<dim3(CC / BN, NT / BM), 256>>>(h1, w2e, b2e, moe,
                                                                      NT, CC, FF, gates + e, NE);
            else
                sgemm_k<EPI_GATE_ACC><<<dim3(CC / BN, NT / BM), 256>>>(h1, w2e, b2e, moe,
                                                                       NT, CC, FF, gates + e, NE);
        }
        combine_k<<<NT * CC / 256, 256>>>(x, moe, skip);
    }

    layernorm_k<<<NT, CC>>>(x, lnfg, lnfb, h);
    sgemm_k<EPI_BIAS><<<dim3((VV + BN - 1) / BN, NT / BM), 256>>>(h, Wlm, blm, out,
                                                                  NT, VV, CC, nullptr, 0);
}